// round 14
// baseline (speedup 1.0000x reference)
#include <cuda_runtime.h>
#include <cuda_bf16.h>
#include <cstdint>

#define L    4096
#define TD   128
#define CH   64
#define NH   4
#define HD   32
#define NSB  4
#define NG   (NSB * NH)

typedef unsigned long long u64;

// Scratch (device globals; no runtime allocation)
static __device__ float Qbuf[NSB * L * TD];                 // fp32 q (residual + fp8 source)
static __device__ float Fbuf[NSB * L * TD];                 // fused = (attn + q) * 0.5
static __device__ uint8_t K8[NG * L * HD];                  // [gk][key][fragment-ready bytes]
static __device__ uint8_t V8[NG * L * HD];                  // [gk][key][d] e4m3
static __device__ uint8_t V8t[NG * HD * L];                 // [gk][d][perm-key words] e4m3
static __device__ float WT[3 * CH * TD];                    // transposed weights [w][c][t]

// ---------------------------------------------------------------------------
__device__ __forceinline__ void ffma2(u64 &d, u64 a, u64 b) {
    asm("fma.rn.f32x2 %0, %1, %2, %0;" : "+l"(d) : "l"(a), "l"(b));
}
__device__ __forceinline__ u64 fma2(u64 a, u64 b, u64 c) {
    u64 d;
    asm("fma.rn.f32x2 %0, %1, %2, %3;" : "=l"(d) : "l"(a), "l"(b), "l"(c));
    return d;
}
__device__ __forceinline__ u64 pack2(float x) {
    u64 r;
    unsigned int u = __float_as_uint(x);
    asm("mov.b64 %0, {%1, %1};" : "=l"(r) : "r"(u));
    return r;
}
__device__ __forceinline__ u64 packab(float lo, float hi) {
    u64 r;
    asm("mov.b64 %0, {%1, %2};" : "=l"(r) : "f"(lo), "f"(hi));
    return r;
}
__device__ __forceinline__ void unpack2(u64 d, float &lo, float &hi) {
    unsigned int a, b;
    asm("mov.b64 {%0, %1}, %2;" : "=r"(a), "=r"(b) : "l"(d));
    lo = __uint_as_float(a);
    hi = __uint_as_float(b);
}
// 4 floats -> 4 packed e4m3 bytes (little-endian: v0 in byte0)
__device__ __forceinline__ uint32_t pk4e4m3(float v0, float v1, float v2, float v3) {
    uint16_t lo, hi;
    asm("cvt.rn.satfinite.e4m3x2.f32 %0, %1, %2;" : "=h"(lo) : "f"(v1), "f"(v0));
    asm("cvt.rn.satfinite.e4m3x2.f32 %0, %1, %2;" : "=h"(hi) : "f"(v3), "f"(v2));
    return (uint32_t)lo | ((uint32_t)hi << 16);
}
// two e-pairs (u64 each) -> 4 packed e4m3 bytes
__device__ __forceinline__ uint32_t pk4e4m3_p(u64 p0, u64 p1) {
    float a0, a1, b0, b1;
    unpack2(p0, a0, a1);
    unpack2(p1, b0, b1);
    return pk4e4m3(a0, a1, b0, b1);
}
__device__ __forceinline__ uint8_t f2e4m3(float x) {
    uint16_t r;
    asm("cvt.rn.satfinite.e4m3x2.f32 %0, %1, %2;" : "=h"(r) : "f"(0.0f), "f"(x));
    return (uint8_t)r;
}
__device__ __forceinline__ uint2 lds64(uint32_t addr) {
    uint2 v;
    asm volatile("ld.shared.v2.b32 {%0,%1}, [%2];" : "=r"(v.x), "=r"(v.y) : "r"(addr));
    return v;
}
__device__ __forceinline__ void cp_async16(uint32_t smem, const void* gptr) {
    asm volatile("cp.async.ca.shared.global [%0], [%1], 16;" :: "r"(smem), "l"(gptr));
}
#define CP_COMMIT() asm volatile("cp.async.commit_group;" ::: "memory")

#define MMA_FP8(d, a, b0, b1) \
    asm volatile("mma.sync.aligned.m16n8k32.row.col.f32.e4m3.e4m3.f32 " \
        "{%0,%1,%2,%3}, {%4,%5,%6,%7}, {%8,%9}, {%0,%1,%2,%3};" \
        : "+f"((d)[0]), "+f"((d)[1]), "+f"((d)[2]), "+f"((d)[3]) \
        : "r"((a)[0]), "r"((a)[1]), "r"((a)[2]), "r"((a)[3]), \
          "r"(b0), "r"(b1))

// ---------------------------------------------------------------------------
// Kernel T: weight transpose. WT[w][c][t] = w_src[t][c].
// ---------------------------------------------------------------------------
__global__ void __launch_bounds__(256) wtrans_kernel(
    const float* __restrict__ wq, const float* __restrict__ wk,
    const float* __restrict__ wv)
{
    int idx = blockIdx.x * 256 + threadIdx.x;
    if (idx >= 3 * TD * CH) return;
    int w = idx / (TD * CH);
    int r = idx % (TD * CH);
    int t = r >> 6, c = r & 63;
    const float* src = (w == 0) ? wq : (w == 1) ? wk : wv;
    WT[w * (CH * TD) + c * TD + t] = src[r];
}

// ---------------------------------------------------------------------------
// Kernel A: QKV projection. K8 written in fragment-ready byte order:
// off(d) = ((d&15)>>2)*8 + (d>>4)*4 + (d&3)
// grid (L/16, NSB), block 128.
// ---------------------------------------------------------------------------
__global__ void __launch_bounds__(128) qkv_kernel(
    const float* __restrict__ fct, const float* __restrict__ fpet,
    const float* __restrict__ bq, const float* __restrict__ bk,
    const float* __restrict__ bv)
{
    int v0 = blockIdx.x * 16;
    int sb = blockIdx.y;
    const float* feat = ((sb >> 1) ? fpet : fct) + (sb & 1) * (CH * L);

    __shared__ __align__(8) float xs[CH][16];
    int t = threadIdx.x;
#pragma unroll
    for (int it = 0; it < 8; it++) {
        int idx = t + it * 128;
        xs[idx >> 4][idx & 15] = feat[(idx >> 4) * L + v0 + (idx & 15)];
    }
    __syncthreads();

    u64 aq[8], ak[8], av[8];
    u64 bqi = pack2(bq[t]), bki = pack2(bk[t]), bvi = pack2(bv[t]);
#pragma unroll
    for (int j = 0; j < 8; j++) { aq[j] = bqi; ak[j] = bki; av[j] = bvi; }

    const float* wqc = WT + t;
    const float* wkc = WT + CH * TD + t;
    const float* wvc = WT + 2 * CH * TD + t;
#pragma unroll 8
    for (int c = 0; c < CH; c++) {
        u64 wqp = pack2(wqc[c * TD]);
        u64 wkp = pack2(wkc[c * TD]);
        u64 wvp = pack2(wvc[c * TD]);
        const u64* xp = (const u64*)&xs[c][0];
#pragma unroll
        for (int j = 0; j < 8; j++) {
            u64 x = xp[j];
            ffma2(aq[j], wqp, x);
            ffma2(ak[j], wkp, x);
            ffma2(av[j], wvp, x);
        }
    }

    int h = t >> 5, d = t & 31;
    int koff = ((d & 15) >> 2) * 8 + ((d >> 4) << 2) + (d & 3);
    size_t gk = (size_t)(sb * NH + h);
#pragma unroll
    for (int j = 0; j < 8; j++) {
        float q0, q1, k0, k1, vv0, vv1;
        unpack2(aq[j], q0, q1);
        unpack2(ak[j], k0, k1);
        unpack2(av[j], vv0, vv1);
        int va = v0 + 2 * j, vb = va + 1;
        Qbuf[(sb * L + va) * TD + t] = q0;
        Qbuf[(sb * L + vb) * TD + t] = q1;
        K8[(gk * L + va) * HD + koff] = f2e4m3(k0);
        K8[(gk * L + vb) * HD + koff] = f2e4m3(k1);
        V8[(gk * L + va) * HD + d] = f2e4m3(vv0);
        V8[(gk * L + vb) * HD + d] = f2e4m3(vv1);
    }
}

// ---------------------------------------------------------------------------
// Kernel V: transpose+permute V8 -> V8t (word (w,hi,tg) at byte w*32+tg*8+hi*4
// holds keys {base,base+1,base+8,base+9}, base = w*32+16*hi+2*tg).
// grid (L/128, NG), block 128.
// ---------------------------------------------------------------------------
__global__ void __launch_bounds__(128) vtrans_kernel()
{
    int kt = blockIdx.x, gk = blockIdx.y;
    int tid = threadIdx.x;

    __shared__ uint8_t vs[128 * 32];
    __shared__ uint8_t os[32 * 128];

    {
        const uint4* src = (const uint4*)(V8 + ((size_t)gk * L + kt * 128) * HD);
        uint4* dst = (uint4*)vs;
        dst[tid] = src[tid];
        dst[tid + 128] = src[tid + 128];
    }
    __syncthreads();

    {
        int d = tid & 31;
        int grp = tid >> 5;
#pragma unroll
        for (int wi = 0; wi < 8; wi++) {
            int widx = grp * 8 + wi;
            int w  = widx >> 3;
            int hi = (widx >> 2) & 1;
            int tg = widx & 3;
            int base = w * 32 + 16 * hi + 2 * tg;
            uint32_t b0 = vs[(base + 0) * 32 + d];
            uint32_t b1 = vs[(base + 1) * 32 + d];
            uint32_t b2 = vs[(base + 8) * 32 + d];
            uint32_t b3 = vs[(base + 9) * 32 + d];
            *(uint32_t*)(os + d * 128 + w * 32 + tg * 8 + hi * 4) =
                b0 | (b1 << 8) | (b2 << 16) | (b3 << 24);
        }
    }
    __syncthreads();

    {
        uint8_t* outb = V8t + (size_t)gk * HD * L;
#pragma unroll
        for (int it = 0; it < 2; it++) {
            int i = tid + it * 128;
            int d = i >> 3, seg = i & 7;
            *(uint4*)(outb + (size_t)d * L + kt * 128 + seg * 16) =
                *(const uint4*)(os + d * 128 + seg * 16);
        }
    }
}

// ---------------------------------------------------------------------------
// Kernel B: all-fp8 flash cross-attention; 32 query rows per warp (2 A-tiles)
// so each B-fragment load feeds 2x MMAs; staging/barriers amortized 2x.
// grid (L/128, NH, NSB) = 512 blocks, block 128 (4 warps).
// ---------------------------------------------------------------------------
#define BUFSZ 13312   // 4096 (K) + 32*288 (V)

__global__ void __launch_bounds__(128, 4) attn_mma_kernel()
{
    __shared__ __align__(128) uint8_t sm[2][BUFSZ];

    int tid  = threadIdx.x;
    int w5   = tid >> 5;
    int lane = tid & 31;
    int g    = lane >> 2;
    int tg   = lane & 3;

    int qt = blockIdx.x, h = blockIdx.y, sb = blockIdx.z;
    int kvsb = sb ^ 2;

    const uint8_t* K8g  = K8  + (size_t)(kvsb * NH + h) * L * HD;
    const uint8_t* V8tg = V8t + (size_t)(kvsb * NH + h) * HD * L;

    uint32_t smb0 = (uint32_t)__cvta_generic_to_shared(&sm[0][0]);
    uint32_t smb1 = (uint32_t)__cvta_generic_to_shared(&sm[1][0]);

    int vrow0 = tid >> 3, vseg0 = tid & 7;
    int vrow1 = (tid + 128) >> 3, vseg1 = tid & 7;

    cp_async16(smb0 + tid * 16, K8g + tid * 16);
    cp_async16(smb0 + (tid + 128) * 16, K8g + (size_t)(tid + 128) * 16);
    cp_async16(smb0 + 4096 + vrow0 * 288 + vseg0 * 16,
               V8tg + (size_t)vrow0 * L + vseg0 * 16);
    cp_async16(smb0 + 4096 + vrow1 * 288 + vseg1 * 16,
               V8tg + (size_t)vrow1 * L + vseg1 * 16);
    CP_COMMIT();

    // ---- Q A-fragments for TWO 16-row tiles (rows qrow0..+15, +16..+31) ----
    int qrow0 = qt * 128 + w5 * 32;
    const float* Qp = Qbuf + ((size_t)sb * L + qrow0) * TD + h * HD;
    uint32_t qa0[4], qa1[4];
    {
        float4 r0a = *(const float4*)(Qp + (size_t)g * TD + 4 * tg);
        float4 r1a = *(const float4*)(Qp + (size_t)(g + 8) * TD + 4 * tg);
        float4 r0b = *(const float4*)(Qp + (size_t)g * TD + 16 + 4 * tg);
        float4 r1b = *(const float4*)(Qp + (size_t)(g + 8) * TD + 16 + 4 * tg);
        qa0[0] = pk4e4m3(0.25f * r0a.x, 0.25f * r0a.y, 0.25f * r0a.z, 0.25f * r0a.w);
        qa0[1] = pk4e4m3(0.25f * r1a.x, 0.25f * r1a.y, 0.25f * r1a.z, 0.25f * r1a.w);
        qa0[2] = pk4e4m3(0.25f * r0b.x, 0.25f * r0b.y, 0.25f * r0b.z, 0.25f * r0b.w);
        qa0[3] = pk4e4m3(0.25f * r1b.x, 0.25f * r1b.y, 0.25f * r1b.z, 0.25f * r1b.w);
        r0a = *(const float4*)(Qp + (size_t)(g + 16) * TD + 4 * tg);
        r1a = *(const float4*)(Qp + (size_t)(g + 24) * TD + 4 * tg);
        r0b = *(const float4*)(Qp + (size_t)(g + 16) * TD + 16 + 4 * tg);
        r1b = *(const float4*)(Qp + (size_t)(g + 24) * TD + 16 + 4 * tg);
        qa1[0] = pk4e4m3(0.25f * r0a.x, 0.25f * r0a.y, 0.25f * r0a.z, 0.25f * r0a.w);
        qa1[1] = pk4e4m3(0.25f * r1a.x, 0.25f * r1a.y, 0.25f * r1a.z, 0.25f * r1a.w);
        qa1[2] = pk4e4m3(0.25f * r0b.x, 0.25f * r0b.y, 0.25f * r0b.z, 0.25f * r0b.w);
        qa1[3] = pk4e4m3(0.25f * r1b.x, 0.25f * r1b.y, 0.25f * r1b.z, 0.25f * r1b.w);
    }

    float oaccA[4][4], oaccB[4][4];
#pragma unroll
    for (int i = 0; i < 4; i++)
#pragma unroll
        for (int j = 0; j < 4; j++) { oaccA[i][j] = 0.0f; oaccB[i][j] = 0.0f; }
    float oRA[4] = {0.f, 0.f, 0.f, 0.f};
    float oRB[4] = {0.f, 0.f, 0.f, 0.f};
    const uint32_t ONES = 0x38383838u;     // e4m3 1.0 x4
    const u64 C1 = pack2(0.25f);
    const u64 C2 = pack2(0.70710678f);
    const u64 ONE2 = pack2(1.0f);

    for (int kt = 0; kt < 32; kt++) {
        uint32_t sK = (kt & 1) ? smb1 : smb0;
        if (kt + 1 < 32) {
            uint32_t sN = (kt & 1) ? smb0 : smb1;
            const uint8_t* kp = K8g + (size_t)(kt + 1) * 4096;
            cp_async16(sN + tid * 16, kp + tid * 16);
            cp_async16(sN + (tid + 128) * 16, kp + (size_t)(tid + 128) * 16);
            cp_async16(sN + 4096 + vrow0 * 288 + vseg0 * 16,
                       V8tg + (size_t)vrow0 * L + (kt + 1) * 128 + vseg0 * 16);
            cp_async16(sN + 4096 + vrow1 * 288 + vseg1 * 16,
                       V8tg + (size_t)vrow1 * L + (kt + 1) * 128 + vseg1 * 16);
            CP_COMMIT();
            asm volatile("cp.async.wait_group 1;" ::: "memory");
        } else {
            asm volatile("cp.async.wait_group 0;" ::: "memory");
        }
        __syncthreads();

        uint32_t sV = sK + 4096;
#pragma unroll
        for (int w = 0; w < 4; w++) {
            // ---- S: 4 key n8-tiles x 2 A-tiles = 8 independent MMAs ----
            uint32_t kb = sK + (uint32_t)(w * 32 + g) * 32 + tg * 8;
            uint2 k0 = lds64(kb);
            uint2 k1 = lds64(kb + 256);
            uint2 k2 = lds64(kb + 512);
            uint2 k3 = lds64(kb + 768);
            float dA0[4] = {0.f,0.f,0.f,0.f}, dA1[4] = {0.f,0.f,0.f,0.f};
            float dA2[4] = {0.f,0.f,0.f,0.f}, dA3[4] = {0.f,0.f,0.f,0.f};
            float dB0[4] = {0.f,0.f,0.f,0.f}, dB1[4] = {0.f,0.f,0.f,0.f};
            float dB2[4] = {0.f,0.f,0.f,0.f}, dB3[4] = {0.f,0.f,0.f,0.f};
            MMA_FP8(dA0, qa0, k0.x, k0.y);
            MMA_FP8(dB0, qa1, k0.x, k0.y);
            MMA_FP8(dA1, qa0, k1.x, k1.y);
            MMA_FP8(dB1, qa1, k1.x, k1.y);
            MMA_FP8(dA2, qa0, k2.x, k2.y);
            MMA_FP8(dB2, qa1, k2.x, k2.y);
            MMA_FP8(dA3, qa0, k3.x, k3.y);
            MMA_FP8(dB3, qa1, k3.x, k3.y);

            // V fragments (shared by both A-tiles)
            uint32_t vbr = sV + (uint32_t)g * 288 + w * 32 + tg * 8;
            uint2 v0 = lds64(vbr);
            uint2 v1 = lds64(vbr + 8 * 288);
            uint2 v2 = lds64(vbr + 16 * 288);
            uint2 v3 = lds64(vbr + 24 * 288);

            // ---- softmax + PV for A-tile 0 ----
            {
                u64 xa = packab(dA0[0], dA0[1]);
                u64 xb = packab(dA0[2], dA0[3]);
                u64 xc = packab(dA1[0], dA1[1]);
                u64 xd = packab(dA1[2], dA1[3]);
                u64 xe = packab(dA2[0], dA2[1]);
                u64 xf = packab(dA2[2], dA2[3]);
                u64 xg = packab(dA3[0], dA3[1]);
                u64 xh = packab(dA3[2], dA3[3]);
                xa = fma2(xa, fma2(xa, C1, C2), ONE2);
                xb = fma2(xb, fma2(xb, C1, C2), ONE2);
                xc = fma2(xc, fma2(xc, C1, C2), ONE2);
                xd = fma2(xd, fma2(xd, C1, C2), ONE2);
                xe = fma2(xe, fma2(xe, C1, C2), ONE2);
                xf = fma2(xf, fma2(xf, C1, C2), ONE2);
                xg = fma2(xg, fma2(xg, C1, C2), ONE2);
                xh = fma2(xh, fma2(xh, C1, C2), ONE2);
                uint32_t pa2[4];
                pa2[0] = pk4e4m3_p(xa, xc);
                pa2[1] = pk4e4m3_p(xb, xd);
                pa2[2] = pk4e4m3_p(xe, xg);
                pa2[3] = pk4e4m3_p(xf, xh);
                MMA_FP8(oaccA[0], pa2, v0.x, v0.y);
                MMA_FP8(oaccA[1], pa2, v1.x, v1.y);
                MMA_FP8(oaccA[2], pa2, v2.x, v2.y);
                MMA_FP8(oaccA[3], pa2, v3.x, v3.y);
                MMA_FP8(oRA, pa2, ONES, ONES);
            }
            // ---- softmax + PV for A-tile 1 ----
            {
                u64 xa = packab(dB0[0], dB0[1]);
                u64 xb = packab(dB0[2], dB0[3]);
                u64 xc = packab(dB1[0], dB1[1]);
                u64 xd = packab(dB1[2], dB1[3]);
                u64 xe = packab(dB2[0], dB2[1]);
                u64 xf = packab(dB2[2], dB2[3]);
                u64 xg = packab(dB3[0], dB3[1]);
                u64 xh = packab(dB3[2], dB3[3]);
                xa = fma2(xa, fma2(xa, C1, C2), ONE2);
                xb = fma2(xb, fma2(xb, C1, C2), ONE2);
                xc = fma2(xc, fma2(xc, C1, C2), ONE2);
                xd = fma2(xd, fma2(xd, C1, C2), ONE2);
                xe = fma2(xe, fma2(xe, C1, C2), ONE2);
                xf = fma2(xf, fma2(xf, C1, C2), ONE2);
                xg = fma2(xg, fma2(xg, C1, C2), ONE2);
                xh = fma2(xh, fma2(xh, C1, C2), ONE2);
                uint32_t pa2[4];
                pa2[0] = pk4e4m3_p(xa, xc);
                pa2[1] = pk4e4m3_p(xb, xd);
                pa2[2] = pk4e4m3_p(xe, xg);
                pa2[3] = pk4e4m3_p(xf, xh);
                MMA_FP8(oaccB[0], pa2, v0.x, v0.y);
                MMA_FP8(oaccB[1], pa2, v1.x, v1.y);
                MMA_FP8(oaccB[2], pa2, v2.x, v2.y);
                MMA_FP8(oaccB[3], pa2, v3.x, v3.y);
                MMA_FP8(oRB, pa2, ONES, ONES);
            }
        }
        __syncthreads();
    }

    // ---- normalize (row sums from ones-MMA), residual, write Fbuf ----
    {
        float invA0 = 1.0f / oRA[0];
        float invA1 = 1.0f / oRA[2];
        float invB0 = 1.0f / oRB[0];
        float invB1 = 1.0f / oRB[2];

        int qrow = qrow0 + g;
        const float* qsrc = Qbuf + ((size_t)sb * L + qrow) * TD + h * HD;
        float* fo = Fbuf + ((size_t)sb * L + qrow) * TD + h * HD;

#pragma unroll
        for (int nd = 0; nd < 4; nd++) {
            int col = nd * 8 + tg * 2;
            float2 q0 = *(const float2*)(qsrc + col);
            float2 r0;
            r0.x = 0.5f * (oaccA[nd][0] * invA0 + q0.x);
            r0.y = 0.5f * (oaccA[nd][1] * invA0 + q0.y);
            *(float2*)(fo + col) = r0;

            float2 q1 = *(const float2*)(qsrc + 8 * TD + col);
            float2 r1;
            r1.x = 0.5f * (oaccA[nd][2] * invA1 + q1.x);
            r1.y = 0.5f * (oaccA[nd][3] * invA1 + q1.y);
            *(float2*)(fo + 8 * TD + col) = r1;

            float2 q2 = *(const float2*)(qsrc + 16 * TD + col);
            float2 r2;
            r2.x = 0.5f * (oaccB[nd][0] * invB0 + q2.x);
            r2.y = 0.5f * (oaccB[nd][1] * invB0 + q2.y);
            *(float2*)(fo + 16 * TD + col) = r2;

            float2 q3 = *(const float2*)(qsrc + 24 * TD + col);
            float2 r3;
            r3.x = 0.5f * (oaccB[nd][2] * invB1 + q3.x);
            r3.y = 0.5f * (oaccB[nd][3] * invB1 + q3.y);
            *(float2*)(fo + 24 * TD + col) = r3;
        }
    }
}

// ---------------------------------------------------------------------------
// Kernel C: output projection + residual. grid (L/16, NSB) = 1024 blocks,
// block 256: thread = (voxel vl 0..15, channel-quad cg 0..15).
// ---------------------------------------------------------------------------
__global__ void __launch_bounds__(256) out_kernel(
    const float* __restrict__ fct, const float* __restrict__ fpet,
    const float* __restrict__ wo, const float* __restrict__ bo,
    float* __restrict__ out)
{
    int vt = blockIdx.x;
    int sb = blockIdx.y;
    int tid = threadIdx.x;
    int vl = tid & 15;
    int cg = tid >> 4;             // channels cg*4 .. cg*4+3
    int v = vt * 16 + vl;

    __shared__ float wos[128][66];
    for (int idx = tid; idx < 128 * 64; idx += 256) {
        int c = idx >> 7;
        int t = idx & 127;
        wos[t][c] = wo[idx];
    }
    __syncthreads();

    u64 accp[2];
    accp[0] = 0ull;
    accp[1] = 0ull;

    const float* F = Fbuf + (size_t)sb * L * TD;
#pragma unroll 16
    for (int t = 0; t < 128; t++) {
        float x = F[(size_t)t * L + v];
        u64 xp = pack2(x);
        const u64* wp = (const u64*)&wos[t][cg * 4];
        ffma2(accp[0], xp, wp[0]);
        ffma2(accp[1], xp, wp[1]);
    }

    const float* feat = ((sb >> 1) ? fpet : fct) + (sb & 1) * (CH * L);
    float* o = out + (size_t)sb * CH * L + v;
#pragma unroll
    for (int i = 0; i < 2; i++) {
        float lo, hi;
        unpack2(accp[i], lo, hi);
        int c0 = cg * 4 + 2 * i, c1 = c0 + 1;
        o[(size_t)c0 * L] = feat[(size_t)c0 * L + v] + bo[c0] + lo;
        o[(size_t)c1 * L] = feat[(size_t)c1 * L + v] + bo[c1] + hi;
    }
}

// ---------------------------------------------------------------------------
extern "C" void kernel_launch(void* const* d_in, const int* in_sizes, int n_in,
                              void* d_out, int out_size)
{
    const float* fct  = (const float*)d_in[0];
    const float* fpet = (const float*)d_in[1];
    const float* wq   = (const float*)d_in[2];
    const float* bq   = (const float*)d_in[3];
    const float* wk   = (const float*)d_in[4];
    const float* bk   = (const float*)d_in[5];
    const float* wv   = (const float*)d_in[6];
    const float* bv   = (const float*)d_in[7];
    const float* wo   = (const float*)d_in[8];
    const float* bo   = (const float*)d_in[9];
    float* out = (float*)d_out;

    cudaFuncSetAttribute(attn_mma_kernel,
                         cudaFuncAttributePreferredSharedMemoryCarveout, 100);

    wtrans_kernel<<<(3 * TD * CH + 255) / 256, 256>>>(wq, wk, wv);
    qkv_kernel<<<dim3(L / 16, NSB), 128>>>(fct, fpet, bq, bk, bv);
    vtrans_kernel<<<dim3(L / 128, NG), 128>>>();
    attn_mma_kernel<<<dim3(L / 128, NH, NSB), 128>>>();
    out_kernel<<<dim3(L / 16, NSB), 256>>>(fct, fpet, wo, bo, out);
}

// round 15
// speedup vs baseline: 1.0837x; 1.0837x over previous
#include <cuda_runtime.h>
#include <cuda_bf16.h>
#include <cstdint>

#define L    4096
#define TD   128
#define CH   64
#define NH   4
#define HD   32
#define NSB  4
#define NG   (NSB * NH)

typedef unsigned long long u64;

// Scratch (device globals; no runtime allocation)
static __device__ float Qbuf[NSB * L * TD];                 // fp32 q (residual + fp8 source)
static __device__ float Fbuf[NSB * L * TD];                 // fused = (attn + q) * 0.5
static __device__ uint8_t K8[NG * L * HD];                  // [gk][key][fragment-ready bytes]
static __device__ uint8_t V8[NG * L * HD];                  // [gk][key][d] e4m3
static __device__ uint8_t V8t[NG * HD * L];                 // [gk][d][perm-key words] e4m3
static __device__ float WT[3 * CH * TD];                    // transposed weights [w][c][t]

// ---------------------------------------------------------------------------
__device__ __forceinline__ void ffma2(u64 &d, u64 a, u64 b) {
    asm("fma.rn.f32x2 %0, %1, %2, %0;" : "+l"(d) : "l"(a), "l"(b));
}
__device__ __forceinline__ u64 fma2(u64 a, u64 b, u64 c) {
    u64 d;
    asm("fma.rn.f32x2 %0, %1, %2, %3;" : "=l"(d) : "l"(a), "l"(b), "l"(c));
    return d;
}
__device__ __forceinline__ u64 pack2(float x) {
    u64 r;
    unsigned int u = __float_as_uint(x);
    asm("mov.b64 %0, {%1, %1};" : "=l"(r) : "r"(u));
    return r;
}
__device__ __forceinline__ u64 packab(float lo, float hi) {
    u64 r;
    asm("mov.b64 %0, {%1, %2};" : "=l"(r) : "f"(lo), "f"(hi));
    return r;
}
__device__ __forceinline__ void unpack2(u64 d, float &lo, float &hi) {
    unsigned int a, b;
    asm("mov.b64 {%0, %1}, %2;" : "=r"(a), "=r"(b) : "l"(d));
    lo = __uint_as_float(a);
    hi = __uint_as_float(b);
}
// 4 floats -> 4 packed e4m3 bytes (little-endian: v0 in byte0)
__device__ __forceinline__ uint32_t pk4e4m3(float v0, float v1, float v2, float v3) {
    uint16_t lo, hi;
    asm("cvt.rn.satfinite.e4m3x2.f32 %0, %1, %2;" : "=h"(lo) : "f"(v1), "f"(v0));
    asm("cvt.rn.satfinite.e4m3x2.f32 %0, %1, %2;" : "=h"(hi) : "f"(v3), "f"(v2));
    return (uint32_t)lo | ((uint32_t)hi << 16);
}
// two e-pairs (u64 each) -> 4 packed e4m3 bytes
__device__ __forceinline__ uint32_t pk4e4m3_p(u64 p0, u64 p1) {
    float a0, a1, b0, b1;
    unpack2(p0, a0, a1);
    unpack2(p1, b0, b1);
    return pk4e4m3(a0, a1, b0, b1);
}
__device__ __forceinline__ uint8_t f2e4m3(float x) {
    uint16_t r;
    asm("cvt.rn.satfinite.e4m3x2.f32 %0, %1, %2;" : "=h"(r) : "f"(0.0f), "f"(x));
    return (uint8_t)r;
}
__device__ __forceinline__ uint2 lds64(uint32_t addr) {
    uint2 v;
    asm volatile("ld.shared.v2.b32 {%0,%1}, [%2];" : "=r"(v.x), "=r"(v.y) : "r"(addr));
    return v;
}
__device__ __forceinline__ void cp_async16(uint32_t smem, const void* gptr) {
    asm volatile("cp.async.ca.shared.global [%0], [%1], 16;" :: "r"(smem), "l"(gptr));
}
#define CP_COMMIT() asm volatile("cp.async.commit_group;" ::: "memory")

#define MMA_FP8(d, a, b0, b1) \
    asm volatile("mma.sync.aligned.m16n8k32.row.col.f32.e4m3.e4m3.f32 " \
        "{%0,%1,%2,%3}, {%4,%5,%6,%7}, {%8,%9}, {%0,%1,%2,%3};" \
        : "+f"((d)[0]), "+f"((d)[1]), "+f"((d)[2]), "+f"((d)[3]) \
        : "r"((a)[0]), "r"((a)[1]), "r"((a)[2]), "r"((a)[3]), \
          "r"(b0), "r"(b1))

// ---------------------------------------------------------------------------
// Kernel T: weight transpose. WT[w][c][t] = w_src[t][c].
// ---------------------------------------------------------------------------
__global__ void __launch_bounds__(256) wtrans_kernel(
    const float* __restrict__ wq, const float* __restrict__ wk,
    const float* __restrict__ wv)
{
    int idx = blockIdx.x * 256 + threadIdx.x;
    if (idx >= 3 * TD * CH) return;
    int w = idx / (TD * CH);
    int r = idx % (TD * CH);
    int t = r >> 6, c = r & 63;
    const float* src = (w == 0) ? wq : (w == 1) ? wk : wv;
    WT[w * (CH * TD) + c * TD + t] = src[r];
}

// ---------------------------------------------------------------------------
// Kernel A: QKV projection. K8 written in fragment-ready byte order:
// off(d) = ((d&15)>>2)*8 + (d>>4)*4 + (d&3)
// grid (L/16, NSB), block 128.
// ---------------------------------------------------------------------------
__global__ void __launch_bounds__(128) qkv_kernel(
    const float* __restrict__ fct, const float* __restrict__ fpet,
    const float* __restrict__ bq, const float* __restrict__ bk,
    const float* __restrict__ bv)
{
    int v0 = blockIdx.x * 16;
    int sb = blockIdx.y;
    const float* feat = ((sb >> 1) ? fpet : fct) + (sb & 1) * (CH * L);

    __shared__ __align__(8) float xs[CH][16];
    int t = threadIdx.x;
#pragma unroll
    for (int it = 0; it < 8; it++) {
        int idx = t + it * 128;
        xs[idx >> 4][idx & 15] = feat[(idx >> 4) * L + v0 + (idx & 15)];
    }
    __syncthreads();

    u64 aq[8], ak[8], av[8];
    u64 bqi = pack2(bq[t]), bki = pack2(bk[t]), bvi = pack2(bv[t]);
#pragma unroll
    for (int j = 0; j < 8; j++) { aq[j] = bqi; ak[j] = bki; av[j] = bvi; }

    const float* wqc = WT + t;
    const float* wkc = WT + CH * TD + t;
    const float* wvc = WT + 2 * CH * TD + t;
#pragma unroll 8
    for (int c = 0; c < CH; c++) {
        u64 wqp = pack2(wqc[c * TD]);
        u64 wkp = pack2(wkc[c * TD]);
        u64 wvp = pack2(wvc[c * TD]);
        const u64* xp = (const u64*)&xs[c][0];
#pragma unroll
        for (int j = 0; j < 8; j++) {
            u64 x = xp[j];
            ffma2(aq[j], wqp, x);
            ffma2(ak[j], wkp, x);
            ffma2(av[j], wvp, x);
        }
    }

    int h = t >> 5, d = t & 31;
    int koff = ((d & 15) >> 2) * 8 + ((d >> 4) << 2) + (d & 3);
    size_t gk = (size_t)(sb * NH + h);
#pragma unroll
    for (int j = 0; j < 8; j++) {
        float q0, q1, k0, k1, vv0, vv1;
        unpack2(aq[j], q0, q1);
        unpack2(ak[j], k0, k1);
        unpack2(av[j], vv0, vv1);
        int va = v0 + 2 * j, vb = va + 1;
        Qbuf[(sb * L + va) * TD + t] = q0;
        Qbuf[(sb * L + vb) * TD + t] = q1;
        K8[(gk * L + va) * HD + koff] = f2e4m3(k0);
        K8[(gk * L + vb) * HD + koff] = f2e4m3(k1);
        V8[(gk * L + va) * HD + d] = f2e4m3(vv0);
        V8[(gk * L + vb) * HD + d] = f2e4m3(vv1);
    }
}

// ---------------------------------------------------------------------------
// Kernel V: transpose+permute V8 -> V8t (word (w,hi,tg) at byte w*32+tg*8+hi*4
// holds keys {base,base+1,base+8,base+9}, base = w*32+16*hi+2*tg).
// grid (L/128, NG), block 128.
// ---------------------------------------------------------------------------
__global__ void __launch_bounds__(128) vtrans_kernel()
{
    int kt = blockIdx.x, gk = blockIdx.y;
    int tid = threadIdx.x;

    __shared__ uint8_t vs[128 * 32];
    __shared__ uint8_t os[32 * 128];

    {
        const uint4* src = (const uint4*)(V8 + ((size_t)gk * L + kt * 128) * HD);
        uint4* dst = (uint4*)vs;
        dst[tid] = src[tid];
        dst[tid + 128] = src[tid + 128];
    }
    __syncthreads();

    {
        int d = tid & 31;
        int grp = tid >> 5;
#pragma unroll
        for (int wi = 0; wi < 8; wi++) {
            int widx = grp * 8 + wi;
            int w  = widx >> 3;
            int hi = (widx >> 2) & 1;
            int tg = widx & 3;
            int base = w * 32 + 16 * hi + 2 * tg;
            uint32_t b0 = vs[(base + 0) * 32 + d];
            uint32_t b1 = vs[(base + 1) * 32 + d];
            uint32_t b2 = vs[(base + 8) * 32 + d];
            uint32_t b3 = vs[(base + 9) * 32 + d];
            *(uint32_t*)(os + d * 128 + w * 32 + tg * 8 + hi * 4) =
                b0 | (b1 << 8) | (b2 << 16) | (b3 << 24);
        }
    }
    __syncthreads();

    {
        uint8_t* outb = V8t + (size_t)gk * HD * L;
#pragma unroll
        for (int it = 0; it < 2; it++) {
            int i = tid + it * 128;
            int d = i >> 3, seg = i & 7;
            *(uint4*)(outb + (size_t)d * L + kt * 128 + seg * 16) =
                *(const uint4*)(os + d * 128 + seg * 16);
        }
    }
}

// ---------------------------------------------------------------------------
// Kernel B: all-fp8 flash cross-attention; PAIRED key-windows for ILP.
// grid (L/64, NH, NSB) = 1024 blocks, block 128 (4 warps; warp = 16 q rows).
// (Byte-identical to the measured-126.8us R13 version.)
// ---------------------------------------------------------------------------
#define BUFSZ 13312   // 4096 (K) + 32*288 (V)

__global__ void __launch_bounds__(128, 5) attn_mma_kernel()
{
    __shared__ __align__(128) uint8_t sm[2][BUFSZ];

    int tid  = threadIdx.x;
    int w5   = tid >> 5;
    int lane = tid & 31;
    int g    = lane >> 2;
    int tg   = lane & 3;

    int qt = blockIdx.x, h = blockIdx.y, sb = blockIdx.z;
    int kvsb = sb ^ 2;

    const uint8_t* K8g  = K8  + (size_t)(kvsb * NH + h) * L * HD;
    const uint8_t* V8tg = V8t + (size_t)(kvsb * NH + h) * HD * L;

    uint32_t smb0 = (uint32_t)__cvta_generic_to_shared(&sm[0][0]);
    uint32_t smb1 = (uint32_t)__cvta_generic_to_shared(&sm[1][0]);

    int vrow0 = tid >> 3, vseg0 = tid & 7;
    int vrow1 = (tid + 128) >> 3, vseg1 = tid & 7;

    cp_async16(smb0 + tid * 16, K8g + tid * 16);
    cp_async16(smb0 + (tid + 128) * 16, K8g + (size_t)(tid + 128) * 16);
    cp_async16(smb0 + 4096 + vrow0 * 288 + vseg0 * 16,
               V8tg + (size_t)vrow0 * L + vseg0 * 16);
    cp_async16(smb0 + 4096 + vrow1 * 288 + vseg1 * 16,
               V8tg + (size_t)vrow1 * L + vseg1 * 16);
    CP_COMMIT();

    // ---- Q A-fragments: fp32 -> e4m3 with exact 0.25 pre-scale ----
    int qrow0 = qt * 64 + w5 * 16;
    const float* Qp = Qbuf + ((size_t)sb * L + qrow0) * TD + h * HD;
    uint32_t qa[4];
    {
        float4 r0a = *(const float4*)(Qp + (size_t)g * TD + 4 * tg);
        float4 r1a = *(const float4*)(Qp + (size_t)(g + 8) * TD + 4 * tg);
        float4 r0b = *(const float4*)(Qp + (size_t)g * TD + 16 + 4 * tg);
        float4 r1b = *(const float4*)(Qp + (size_t)(g + 8) * TD + 16 + 4 * tg);
        qa[0] = pk4e4m3(0.25f * r0a.x, 0.25f * r0a.y, 0.25f * r0a.z, 0.25f * r0a.w);
        qa[1] = pk4e4m3(0.25f * r1a.x, 0.25f * r1a.y, 0.25f * r1a.z, 0.25f * r1a.w);
        qa[2] = pk4e4m3(0.25f * r0b.x, 0.25f * r0b.y, 0.25f * r0b.z, 0.25f * r0b.w);
        qa[3] = pk4e4m3(0.25f * r1b.x, 0.25f * r1b.y, 0.25f * r1b.z, 0.25f * r1b.w);
    }

    float oacc[4][4];
#pragma unroll
    for (int i = 0; i < 4; i++)
#pragma unroll
        for (int j = 0; j < 4; j++) oacc[i][j] = 0.0f;
    float oaccR[4] = {0.f, 0.f, 0.f, 0.f};
    const uint32_t ONES = 0x38383838u;     // e4m3 1.0 x4
    const u64 C1 = pack2(0.25f);
    const u64 C2 = pack2(0.70710678f);
    const u64 ONE2 = pack2(1.0f);

    for (int kt = 0; kt < 32; kt++) {
        uint32_t sK = (kt & 1) ? smb1 : smb0;
        if (kt + 1 < 32) {
            uint32_t sN = (kt & 1) ? smb0 : smb1;
            const uint8_t* kp = K8g + (size_t)(kt + 1) * 4096;
            cp_async16(sN + tid * 16, kp + tid * 16);
            cp_async16(sN + (tid + 128) * 16, kp + (size_t)(tid + 128) * 16);
            cp_async16(sN + 4096 + vrow0 * 288 + vseg0 * 16,
                       V8tg + (size_t)vrow0 * L + (kt + 1) * 128 + vseg0 * 16);
            cp_async16(sN + 4096 + vrow1 * 288 + vseg1 * 16,
                       V8tg + (size_t)vrow1 * L + (kt + 1) * 128 + vseg1 * 16);
            CP_COMMIT();
            asm volatile("cp.async.wait_group 1;" ::: "memory");
        } else {
            asm volatile("cp.async.wait_group 0;" ::: "memory");
        }
        __syncthreads();

        uint32_t sV = sK + 4096;
#pragma unroll
        for (int wp = 0; wp < 2; wp++) {
            // ======== paired windows A (keys wp*64..+31) and B (+32..+63) ====
            uint32_t kbA = sK + (uint32_t)(wp * 64 + g) * 32 + tg * 8;
            // ---- S MMAs for BOTH windows up front (8 independent MMAs) ----
            uint2 ka0 = lds64(kbA);
            uint2 ka1 = lds64(kbA + 256);
            uint2 ka2 = lds64(kbA + 512);
            uint2 ka3 = lds64(kbA + 768);
            uint2 kb0 = lds64(kbA + 1024);
            uint2 kb1 = lds64(kbA + 1280);
            uint2 kb2 = lds64(kbA + 1536);
            uint2 kb3 = lds64(kbA + 1792);
            float dA0[4] = {0.f,0.f,0.f,0.f}, dA1[4] = {0.f,0.f,0.f,0.f};
            float dA2[4] = {0.f,0.f,0.f,0.f}, dA3[4] = {0.f,0.f,0.f,0.f};
            float dB0[4] = {0.f,0.f,0.f,0.f}, dB1[4] = {0.f,0.f,0.f,0.f};
            float dB2[4] = {0.f,0.f,0.f,0.f}, dB3[4] = {0.f,0.f,0.f,0.f};
            MMA_FP8(dA0, qa, ka0.x, ka0.y);
            MMA_FP8(dA1, qa, ka1.x, ka1.y);
            MMA_FP8(dA2, qa, ka2.x, ka2.y);
            MMA_FP8(dA3, qa, ka3.x, ka3.y);
            MMA_FP8(dB0, qa, kb0.x, kb0.y);
            MMA_FP8(dB1, qa, kb1.x, kb1.y);
            MMA_FP8(dB2, qa, kb2.x, kb2.y);
            MMA_FP8(dB3, qa, kb3.x, kb3.y);

            // ---- softmax + PV for window A (B's S-MMAs still in flight) ----
            {
                u64 xa = packab(dA0[0], dA0[1]);
                u64 xb = packab(dA0[2], dA0[3]);
                u64 xc = packab(dA1[0], dA1[1]);
                u64 xd = packab(dA1[2], dA1[3]);
                u64 xe = packab(dA2[0], dA2[1]);
                u64 xf = packab(dA2[2], dA2[3]);
                u64 xg = packab(dA3[0], dA3[1]);
                u64 xh = packab(dA3[2], dA3[3]);
                xa = fma2(xa, fma2(xa, C1, C2), ONE2);
                xb = fma2(xb, fma2(xb, C1, C2), ONE2);
                xc = fma2(xc, fma2(xc, C1, C2), ONE2);
                xd = fma2(xd, fma2(xd, C1, C2), ONE2);
                xe = fma2(xe, fma2(xe, C1, C2), ONE2);
                xf = fma2(xf, fma2(xf, C1, C2), ONE2);
                xg = fma2(xg, fma2(xg, C1, C2), ONE2);
                xh = fma2(xh, fma2(xh, C1, C2), ONE2);
                uint32_t pa2[4];
                pa2[0] = pk4e4m3_p(xa, xc);
                pa2[1] = pk4e4m3_p(xb, xd);
                pa2[2] = pk4e4m3_p(xe, xg);
                pa2[3] = pk4e4m3_p(xf, xh);

                uint32_t vb = sV + (uint32_t)g * 288 + wp * 64 + tg * 8;
                uint2 v0 = lds64(vb);
                uint2 v1 = lds64(vb + 8 * 288);
                uint2 v2 = lds64(vb + 16 * 288);
                uint2 v3 = lds64(vb + 24 * 288);
                MMA_FP8(oacc[0], pa2, v0.x, v0.y);
                MMA_FP8(oacc[1], pa2, v1.x, v1.y);
                MMA_FP8(oacc[2], pa2, v2.x, v2.y);
                MMA_FP8(oacc[3], pa2, v3.x, v3.y);
                MMA_FP8(oaccR, pa2, ONES, ONES);
            }
            // ---- softmax + PV for window B ----
            {
                u64 xa = packab(dB0[0], dB0[1]);
                u64 xb = packab(dB0[2], dB0[3]);
                u64 xc = packab(dB1[0], dB1[1]);
                u64 xd = packab(dB1[2], dB1[3]);
                u64 xe = packab(dB2[0], dB2[1]);
                u64 xf = packab(dB2[2], dB2[3]);
                u64 xg = packab(dB3[0], dB3[1]);
                u64 xh = packab(dB3[2], dB3[3]);
                xa = fma2(xa, fma2(xa, C1, C2), ONE2);
                xb = fma2(xb, fma2(xb, C1, C2), ONE2);
                xc = fma2(xc, fma2(xc, C1, C2), ONE2);
                xd = fma2(xd, fma2(xd, C1, C2), ONE2);
                xe = fma2(xe, fma2(xe, C1, C2), ONE2);
                xf = fma2(xf, fma2(xf, C1, C2), ONE2);
                xg = fma2(xg, fma2(xg, C1, C2), ONE2);
                xh = fma2(xh, fma2(xh, C1, C2), ONE2);
                uint32_t pa2[4];
                pa2[0] = pk4e4m3_p(xa, xc);
                pa2[1] = pk4e4m3_p(xb, xd);
                pa2[2] = pk4e4m3_p(xe, xg);
                pa2[3] = pk4e4m3_p(xf, xh);

                uint32_t vb = sV + (uint32_t)g * 288 + wp * 64 + 32 + tg * 8;
                uint2 v0 = lds64(vb);
                uint2 v1 = lds64(vb + 8 * 288);
                uint2 v2 = lds64(vb + 16 * 288);
                uint2 v3 = lds64(vb + 24 * 288);
                MMA_FP8(oacc[0], pa2, v0.x, v0.y);
                MMA_FP8(oacc[1], pa2, v1.x, v1.y);
                MMA_FP8(oacc[2], pa2, v2.x, v2.y);
                MMA_FP8(oacc[3], pa2, v3.x, v3.y);
                MMA_FP8(oaccR, pa2, ONES, ONES);
            }
        }
        __syncthreads();
    }

    // ---- normalize (row sums from ones-MMA), residual, write Fbuf ----
    float inv0 = 1.0f / oaccR[0];
    float inv1 = 1.0f / oaccR[2];

    int qrow = qrow0 + g;
    const float* qsrc = Qbuf + ((size_t)sb * L + qrow) * TD + h * HD;
    float* fo = Fbuf + ((size_t)sb * L + qrow) * TD + h * HD;

#pragma unroll
    for (int nd = 0; nd < 4; nd++) {
        int col = nd * 8 + tg * 2;
        float2 q0 = *(const float2*)(qsrc + col);
        float2 r0;
        r0.x = 0.5f * (oacc[nd][0] * inv0 + q0.x);
        r0.y = 0.5f * (oacc[nd][1] * inv0 + q0.y);
        *(float2*)(fo + col) = r0;

        float2 q1 = *(const float2*)(qsrc + 8 * TD + col);
        float2 r1;
        r1.x = 0.5f * (oacc[nd][2] * inv1 + q1.x);
        r1.y = 0.5f * (oacc[nd][3] * inv1 + q1.y);
        *(float2*)(fo + 8 * TD + col) = r1;
    }
}

// ---------------------------------------------------------------------------
// Kernel C: output projection + residual. grid (L/16, NSB) = 1024 blocks,
// block 256: thread = (voxel vl 0..15, channel-quad cg 0..15).
// (Validated in R14; doubled warp supply on a latency-bound kernel.)
// ---------------------------------------------------------------------------
__global__ void __launch_bounds__(256) out_kernel(
    const float* __restrict__ fct, const float* __restrict__ fpet,
    const float* __restrict__ wo, const float* __restrict__ bo,
    float* __restrict__ out)
{
    int vt = blockIdx.x;
    int sb = blockIdx.y;
    int tid = threadIdx.x;
    int vl = tid & 15;
    int cg = tid >> 4;             // channels cg*4 .. cg*4+3
    int v = vt * 16 + vl;

    __shared__ float wos[128][66];
    for (int idx = tid; idx < 128 * 64; idx += 256) {
        int c = idx >> 7;
        int t = idx & 127;
        wos[t][c] = wo[idx];
    }
    __syncthreads();

    u64 accp[2];
    accp[0] = 0ull;
    accp[1] = 0ull;

    const float* F = Fbuf + (size_t)sb * L * TD;
#pragma unroll 16
    for (int t = 0; t < 128; t++) {
        float x = F[(size_t)t * L + v];
        u64 xp = pack2(x);
        const u64* wp = (const u64*)&wos[t][cg * 4];
        ffma2(accp[0], xp, wp[0]);
        ffma2(accp[1], xp, wp[1]);
    }

    const float* feat = ((sb >> 1) ? fpet : fct) + (sb & 1) * (CH * L);
    float* o = out + (size_t)sb * CH * L + v;
#pragma unroll
    for (int i = 0; i < 2; i++) {
        float lo, hi;
        unpack2(accp[i], lo, hi);
        int c0 = cg * 4 + 2 * i, c1 = c0 + 1;
        o[(size_t)c0 * L] = feat[(size_t)c0 * L + v] + bo[c0] + lo;
        o[(size_t)c1 * L] = feat[(size_t)c1 * L + v] + bo[c1] + hi;
    }
}

// ---------------------------------------------------------------------------
extern "C" void kernel_launch(void* const* d_in, const int* in_sizes, int n_in,
                              void* d_out, int out_size)
{
    const float* fct  = (const float*)d_in[0];
    const float* fpet = (const float*)d_in[1];
    const float* wq   = (const float*)d_in[2];
    const float* bq   = (const float*)d_in[3];
    const float* wk   = (const float*)d_in[4];
    const float* bk   = (const float*)d_in[5];
    const float* wv   = (const float*)d_in[6];
    const float* bv   = (const float*)d_in[7];
    const float* wo   = (const float*)d_in[8];
    const float* bo   = (const float*)d_in[9];
    float* out = (float*)d_out;

    cudaFuncSetAttribute(attn_mma_kernel,
                         cudaFuncAttributePreferredSharedMemoryCarveout, 100);

    wtrans_kernel<<<(3 * TD * CH + 255) / 256, 256>>>(wq, wk, wv);
    qkv_kernel<<<dim3(L / 16, NSB), 128>>>(fct, fpet, bq, bk, bv);
    vtrans_kernel<<<dim3(L / 128, NG), 128>>>();
    attn_mma_kernel<<<dim3(L / 64, NH, NSB), 128>>>();
    out_kernel<<<dim3(L / 16, NSB), 256>>>(fct, fpet, wo, bo, out);
}

// round 16
// speedup vs baseline: 1.1312x; 1.0438x over previous
#include <cuda_runtime.h>
#include <cuda_bf16.h>
#include <cstdint>

#define L    4096
#define TD   128
#define CH   64
#define NH   4
#define HD   32
#define NSB  4
#define NG   (NSB * NH)

typedef unsigned long long u64;

// Scratch (device globals; no runtime allocation)
static __device__ float Qbuf[NSB * L * TD];                 // fp32 q (residual + fp8 source)
static __device__ float Fbuf[NSB * L * TD];                 // fused = (attn + q) * 0.5
static __device__ uint8_t K8[NG * L * HD];                  // [gk][key][fragment-ready bytes]
static __device__ uint8_t V8t[NG * HD * L];                 // [gk][d][perm-key words] e4m3
static __device__ float WT[3 * CH * TD];                    // transposed weights [w][c][t]

// ---------------------------------------------------------------------------
__device__ __forceinline__ void ffma2(u64 &d, u64 a, u64 b) {
    asm("fma.rn.f32x2 %0, %1, %2, %0;" : "+l"(d) : "l"(a), "l"(b));
}
__device__ __forceinline__ u64 fma2(u64 a, u64 b, u64 c) {
    u64 d;
    asm("fma.rn.f32x2 %0, %1, %2, %3;" : "=l"(d) : "l"(a), "l"(b), "l"(c));
    return d;
}
__device__ __forceinline__ u64 pack2(float x) {
    u64 r;
    unsigned int u = __float_as_uint(x);
    asm("mov.b64 %0, {%1, %1};" : "=l"(r) : "r"(u));
    return r;
}
__device__ __forceinline__ u64 packab(float lo, float hi) {
    u64 r;
    asm("mov.b64 %0, {%1, %2};" : "=l"(r) : "f"(lo), "f"(hi));
    return r;
}
__device__ __forceinline__ void unpack2(u64 d, float &lo, float &hi) {
    unsigned int a, b;
    asm("mov.b64 {%0, %1}, %2;" : "=r"(a), "=r"(b) : "l"(d));
    lo = __uint_as_float(a);
    hi = __uint_as_float(b);
}
// 4 floats -> 4 packed e4m3 bytes (little-endian: v0 in byte0)
__device__ __forceinline__ uint32_t pk4e4m3(float v0, float v1, float v2, float v3) {
    uint16_t lo, hi;
    asm("cvt.rn.satfinite.e4m3x2.f32 %0, %1, %2;" : "=h"(lo) : "f"(v1), "f"(v0));
    asm("cvt.rn.satfinite.e4m3x2.f32 %0, %1, %2;" : "=h"(hi) : "f"(v3), "f"(v2));
    return (uint32_t)lo | ((uint32_t)hi << 16);
}
// two e-pairs (u64 each) -> 4 packed e4m3 bytes
__device__ __forceinline__ uint32_t pk4e4m3_p(u64 p0, u64 p1) {
    float a0, a1, b0, b1;
    unpack2(p0, a0, a1);
    unpack2(p1, b0, b1);
    return pk4e4m3(a0, a1, b0, b1);
}
__device__ __forceinline__ uint8_t f2e4m3(float x) {
    uint16_t r;
    asm("cvt.rn.satfinite.e4m3x2.f32 %0, %1, %2;" : "=h"(r) : "f"(0.0f), "f"(x));
    return (uint8_t)r;
}
__device__ __forceinline__ uint2 lds64(uint32_t addr) {
    uint2 v;
    asm volatile("ld.shared.v2.b32 {%0,%1}, [%2];" : "=r"(v.x), "=r"(v.y) : "r"(addr));
    return v;
}
__device__ __forceinline__ void cp_async16(uint32_t smem, const void* gptr) {
    asm volatile("cp.async.ca.shared.global [%0], [%1], 16;" :: "r"(smem), "l"(gptr));
}
#define CP_COMMIT() asm volatile("cp.async.commit_group;" ::: "memory")

#define MMA_FP8(d, a, b0, b1) \
    asm volatile("mma.sync.aligned.m16n8k32.row.col.f32.e4m3.e4m3.f32 " \
        "{%0,%1,%2,%3}, {%4,%5,%6,%7}, {%8,%9}, {%0,%1,%2,%3};" \
        : "+f"((d)[0]), "+f"((d)[1]), "+f"((d)[2]), "+f"((d)[3]) \
        : "r"((a)[0]), "r"((a)[1]), "r"((a)[2]), "r"((a)[3]), \
          "r"(b0), "r"(b1))

// ---------------------------------------------------------------------------
// Kernel T: weight transpose. WT[w][c][t] = w_src[t][c].
// ---------------------------------------------------------------------------
__global__ void __launch_bounds__(256) wtrans_kernel(
    const float* __restrict__ wq, const float* __restrict__ wk,
    const float* __restrict__ wv)
{
    int idx = blockIdx.x * 256 + threadIdx.x;
    if (idx >= 3 * TD * CH) return;
    int w = idx / (TD * CH);
    int r = idx % (TD * CH);
    int t = r >> 6, c = r & 63;
    const float* src = (w == 0) ? wq : (w == 1) ? wk : wv;
    WT[w * (CH * TD) + c * TD + t] = src[r];
}

// ---------------------------------------------------------------------------
// Kernel A: QKV projection + FUSED V transpose/permute.
// Thread t owns (h = t>>5, d = t&31) and all 16 voxels of the block, so the
// 4 permuted V8t words (keys {2tg,2tg+1,2tg+8,2tg+9} of this 16-key window)
// are built entirely from registers. K8 in fragment-ready order as before.
// grid (L/16, NSB), block 128.
// ---------------------------------------------------------------------------
__global__ void __launch_bounds__(128) qkv_kernel(
    const float* __restrict__ fct, const float* __restrict__ fpet,
    const float* __restrict__ bq, const float* __restrict__ bk,
    const float* __restrict__ bv)
{
    int v0 = blockIdx.x * 16;
    int sb = blockIdx.y;
    const float* feat = ((sb >> 1) ? fpet : fct) + (sb & 1) * (CH * L);

    __shared__ __align__(8) float xs[CH][16];
    int t = threadIdx.x;
#pragma unroll
    for (int it = 0; it < 8; it++) {
        int idx = t + it * 128;
        xs[idx >> 4][idx & 15] = feat[(idx >> 4) * L + v0 + (idx & 15)];
    }
    __syncthreads();

    u64 aq[8], ak[8], av[8];
    u64 bqi = pack2(bq[t]), bki = pack2(bk[t]), bvi = pack2(bv[t]);
#pragma unroll
    for (int j = 0; j < 8; j++) { aq[j] = bqi; ak[j] = bki; av[j] = bvi; }

    const float* wqc = WT + t;
    const float* wkc = WT + CH * TD + t;
    const float* wvc = WT + 2 * CH * TD + t;
#pragma unroll 8
    for (int c = 0; c < CH; c++) {
        u64 wqp = pack2(wqc[c * TD]);
        u64 wkp = pack2(wkc[c * TD]);
        u64 wvp = pack2(wvc[c * TD]);
        const u64* xp = (const u64*)&xs[c][0];
#pragma unroll
        for (int j = 0; j < 8; j++) {
            u64 x = xp[j];
            ffma2(aq[j], wqp, x);
            ffma2(ak[j], wkp, x);
            ffma2(av[j], wvp, x);
        }
    }

    int h = t >> 5, d = t & 31;
    int koff = ((d & 15) >> 2) * 8 + ((d >> 4) << 2) + (d & 3);
    size_t gk = (size_t)(sb * NH + h);

    float lv[16];   // local V values per key
#pragma unroll
    for (int j = 0; j < 8; j++) {
        float q0, q1, k0, k1;
        unpack2(aq[j], q0, q1);
        unpack2(ak[j], k0, k1);
        unpack2(av[j], lv[2 * j], lv[2 * j + 1]);
        int va = v0 + 2 * j, vb = va + 1;
        Qbuf[(sb * L + va) * TD + t] = q0;
        Qbuf[(sb * L + vb) * TD + t] = q1;
        K8[(gk * L + va) * HD + koff] = f2e4m3(k0);
        K8[(gk * L + vb) * HD + koff] = f2e4m3(k1);
    }

    // fused V8t write: 4 words covering this 16-key window for dim d
    {
        uint8_t* vt = V8t + gk * HD * L + (size_t)d * L
                    + ((v0 >> 5) << 5) + (((v0 >> 4) & 1) << 2);
#pragma unroll
        for (int tg = 0; tg < 4; tg++) {
            uint32_t wd = pk4e4m3(lv[2 * tg], lv[2 * tg + 1],
                                  lv[2 * tg + 8], lv[2 * tg + 9]);
            *(uint32_t*)(vt + tg * 8) = wd;
        }
    }
}

// ---------------------------------------------------------------------------
// Kernel B: all-fp8 flash cross-attention; PAIRED key-windows for ILP.
// grid (L/64, NH, NSB) = 1024 blocks, block 128 (4 warps; warp = 16 q rows).
// (Byte-identical inner loop to the measured-126.8us R13 version.)
// ---------------------------------------------------------------------------
#define BUFSZ 13312   // 4096 (K) + 32*288 (V)

__global__ void __launch_bounds__(128, 5) attn_mma_kernel()
{
    __shared__ __align__(128) uint8_t sm[2][BUFSZ];

    int tid  = threadIdx.x;
    int w5   = tid >> 5;
    int lane = tid & 31;
    int g    = lane >> 2;
    int tg   = lane & 3;

    int qt = blockIdx.x, h = blockIdx.y, sb = blockIdx.z;
    int kvsb = sb ^ 2;

    const uint8_t* K8g  = K8  + (size_t)(kvsb * NH + h) * L * HD;
    const uint8_t* V8tg = V8t + (size_t)(kvsb * NH + h) * HD * L;

    uint32_t smb0 = (uint32_t)__cvta_generic_to_shared(&sm[0][0]);
    uint32_t smb1 = (uint32_t)__cvta_generic_to_shared(&sm[1][0]);

    int vrow0 = tid >> 3, vseg0 = tid & 7;
    int vrow1 = (tid + 128) >> 3, vseg1 = tid & 7;

    cp_async16(smb0 + tid * 16, K8g + tid * 16);
    cp_async16(smb0 + (tid + 128) * 16, K8g + (size_t)(tid + 128) * 16);
    cp_async16(smb0 + 4096 + vrow0 * 288 + vseg0 * 16,
               V8tg + (size_t)vrow0 * L + vseg0 * 16);
    cp_async16(smb0 + 4096 + vrow1 * 288 + vseg1 * 16,
               V8tg + (size_t)vrow1 * L + vseg1 * 16);
    CP_COMMIT();

    // ---- Q A-fragments: fp32 -> e4m3 with exact 0.25 pre-scale ----
    int qrow0 = qt * 64 + w5 * 16;
    const float* Qp = Qbuf + ((size_t)sb * L + qrow0) * TD + h * HD;
    uint32_t qa[4];
    {
        float4 r0a = *(const float4*)(Qp + (size_t)g * TD + 4 * tg);
        float4 r1a = *(const float4*)(Qp + (size_t)(g + 8) * TD + 4 * tg);
        float4 r0b = *(const float4*)(Qp + (size_t)g * TD + 16 + 4 * tg);
        float4 r1b = *(const float4*)(Qp + (size_t)(g + 8) * TD + 16 + 4 * tg);
        qa[0] = pk4e4m3(0.25f * r0a.x, 0.25f * r0a.y, 0.25f * r0a.z, 0.25f * r0a.w);
        qa[1] = pk4e4m3(0.25f * r1a.x, 0.25f * r1a.y, 0.25f * r1a.z, 0.25f * r1a.w);
        qa[2] = pk4e4m3(0.25f * r0b.x, 0.25f * r0b.y, 0.25f * r0b.z, 0.25f * r0b.w);
        qa[3] = pk4e4m3(0.25f * r1b.x, 0.25f * r1b.y, 0.25f * r1b.z, 0.25f * r1b.w);
    }

    float oacc[4][4];
#pragma unroll
    for (int i = 0; i < 4; i++)
#pragma unroll
        for (int j = 0; j < 4; j++) oacc[i][j] = 0.0f;
    float oaccR[4] = {0.f, 0.f, 0.f, 0.f};
    const uint32_t ONES = 0x38383838u;     // e4m3 1.0 x4
    const u64 C1 = pack2(0.25f);
    const u64 C2 = pack2(0.70710678f);
    const u64 ONE2 = pack2(1.0f);

    for (int kt = 0; kt < 32; kt++) {
        uint32_t sK = (kt & 1) ? smb1 : smb0;
        if (kt + 1 < 32) {
            uint32_t sN = (kt & 1) ? smb0 : smb1;
            const uint8_t* kp = K8g + (size_t)(kt + 1) * 4096;
            cp_async16(sN + tid * 16, kp + tid * 16);
            cp_async16(sN + (tid + 128) * 16, kp + (size_t)(tid + 128) * 16);
            cp_async16(sN + 4096 + vrow0 * 288 + vseg0 * 16,
                       V8tg + (size_t)vrow0 * L + (kt + 1) * 128 + vseg0 * 16);
            cp_async16(sN + 4096 + vrow1 * 288 + vseg1 * 16,
                       V8tg + (size_t)vrow1 * L + (kt + 1) * 128 + vseg1 * 16);
            CP_COMMIT();
            asm volatile("cp.async.wait_group 1;" ::: "memory");
        } else {
            asm volatile("cp.async.wait_group 0;" ::: "memory");
        }
        __syncthreads();

        uint32_t sV = sK + 4096;
#pragma unroll
        for (int wp = 0; wp < 2; wp++) {
            uint32_t kbA = sK + (uint32_t)(wp * 64 + g) * 32 + tg * 8;
            uint2 ka0 = lds64(kbA);
            uint2 ka1 = lds64(kbA + 256);
            uint2 ka2 = lds64(kbA + 512);
            uint2 ka3 = lds64(kbA + 768);
            uint2 kb0 = lds64(kbA + 1024);
            uint2 kb1 = lds64(kbA + 1280);
            uint2 kb2 = lds64(kbA + 1536);
            uint2 kb3 = lds64(kbA + 1792);
            float dA0[4] = {0.f,0.f,0.f,0.f}, dA1[4] = {0.f,0.f,0.f,0.f};
            float dA2[4] = {0.f,0.f,0.f,0.f}, dA3[4] = {0.f,0.f,0.f,0.f};
            float dB0[4] = {0.f,0.f,0.f,0.f}, dB1[4] = {0.f,0.f,0.f,0.f};
            float dB2[4] = {0.f,0.f,0.f,0.f}, dB3[4] = {0.f,0.f,0.f,0.f};
            MMA_FP8(dA0, qa, ka0.x, ka0.y);
            MMA_FP8(dA1, qa, ka1.x, ka1.y);
            MMA_FP8(dA2, qa, ka2.x, ka2.y);
            MMA_FP8(dA3, qa, ka3.x, ka3.y);
            MMA_FP8(dB0, qa, kb0.x, kb0.y);
            MMA_FP8(dB1, qa, kb1.x, kb1.y);
            MMA_FP8(dB2, qa, kb2.x, kb2.y);
            MMA_FP8(dB3, qa, kb3.x, kb3.y);

            {
                u64 xa = packab(dA0[0], dA0[1]);
                u64 xb = packab(dA0[2], dA0[3]);
                u64 xc = packab(dA1[0], dA1[1]);
                u64 xd = packab(dA1[2], dA1[3]);
                u64 xe = packab(dA2[0], dA2[1]);
                u64 xf = packab(dA2[2], dA2[3]);
                u64 xg = packab(dA3[0], dA3[1]);
                u64 xh = packab(dA3[2], dA3[3]);
                xa = fma2(xa, fma2(xa, C1, C2), ONE2);
                xb = fma2(xb, fma2(xb, C1, C2), ONE2);
                xc = fma2(xc, fma2(xc, C1, C2), ONE2);
                xd = fma2(xd, fma2(xd, C1, C2), ONE2);
                xe = fma2(xe, fma2(xe, C1, C2), ONE2);
                xf = fma2(xf, fma2(xf, C1, C2), ONE2);
                xg = fma2(xg, fma2(xg, C1, C2), ONE2);
                xh = fma2(xh, fma2(xh, C1, C2), ONE2);
                uint32_t pa2[4];
                pa2[0] = pk4e4m3_p(xa, xc);
                pa2[1] = pk4e4m3_p(xb, xd);
                pa2[2] = pk4e4m3_p(xe, xg);
                pa2[3] = pk4e4m3_p(xf, xh);

                uint32_t vb = sV + (uint32_t)g * 288 + wp * 64 + tg * 8;
                uint2 v0 = lds64(vb);
                uint2 v1 = lds64(vb + 8 * 288);
                uint2 v2 = lds64(vb + 16 * 288);
                uint2 v3 = lds64(vb + 24 * 288);
                MMA_FP8(oacc[0], pa2, v0.x, v0.y);
                MMA_FP8(oacc[1], pa2, v1.x, v1.y);
                MMA_FP8(oacc[2], pa2, v2.x, v2.y);
                MMA_FP8(oacc[3], pa2, v3.x, v3.y);
                MMA_FP8(oaccR, pa2, ONES, ONES);
            }
            {
                u64 xa = packab(dB0[0], dB0[1]);
                u64 xb = packab(dB0[2], dB0[3]);
                u64 xc = packab(dB1[0], dB1[1]);
                u64 xd = packab(dB1[2], dB1[3]);
                u64 xe = packab(dB2[0], dB2[1]);
                u64 xf = packab(dB2[2], dB2[3]);
                u64 xg = packab(dB3[0], dB3[1]);
                u64 xh = packab(dB3[2], dB3[3]);
                xa = fma2(xa, fma2(xa, C1, C2), ONE2);
                xb = fma2(xb, fma2(xb, C1, C2), ONE2);
                xc = fma2(xc, fma2(xc, C1, C2), ONE2);
                xd = fma2(xd, fma2(xd, C1, C2), ONE2);
                xe = fma2(xe, fma2(xe, C1, C2), ONE2);
                xf = fma2(xf, fma2(xf, C1, C2), ONE2);
                xg = fma2(xg, fma2(xg, C1, C2), ONE2);
                xh = fma2(xh, fma2(xh, C1, C2), ONE2);
                uint32_t pa2[4];
                pa2[0] = pk4e4m3_p(xa, xc);
                pa2[1] = pk4e4m3_p(xb, xd);
                pa2[2] = pk4e4m3_p(xe, xg);
                pa2[3] = pk4e4m3_p(xf, xh);

                uint32_t vb = sV + (uint32_t)g * 288 + wp * 64 + 32 + tg * 8;
                uint2 v0 = lds64(vb);
                uint2 v1 = lds64(vb + 8 * 288);
                uint2 v2 = lds64(vb + 16 * 288);
                uint2 v3 = lds64(vb + 24 * 288);
                MMA_FP8(oacc[0], pa2, v0.x, v0.y);
                MMA_FP8(oacc[1], pa2, v1.x, v1.y);
                MMA_FP8(oacc[2], pa2, v2.x, v2.y);
                MMA_FP8(oacc[3], pa2, v3.x, v3.y);
                MMA_FP8(oaccR, pa2, ONES, ONES);
            }
        }
        __syncthreads();
    }

    // ---- normalize (row sums from ones-MMA), residual, write Fbuf ----
    float inv0 = 1.0f / oaccR[0];
    float inv1 = 1.0f / oaccR[2];

    int qrow = qrow0 + g;
    const float* qsrc = Qbuf + ((size_t)sb * L + qrow) * TD + h * HD;
    float* fo = Fbuf + ((size_t)sb * L + qrow) * TD + h * HD;

#pragma unroll
    for (int nd = 0; nd < 4; nd++) {
        int col = nd * 8 + tg * 2;
        float2 q0 = *(const float2*)(qsrc + col);
        float2 r0;
        r0.x = 0.5f * (oacc[nd][0] * inv0 + q0.x);
        r0.y = 0.5f * (oacc[nd][1] * inv0 + q0.y);
        *(float2*)(fo + col) = r0;

        float2 q1 = *(const float2*)(qsrc + 8 * TD + col);
        float2 r1;
        r1.x = 0.5f * (oacc[nd][2] * inv1 + q1.x);
        r1.y = 0.5f * (oacc[nd][3] * inv1 + q1.y);
        *(float2*)(fo + 8 * TD + col) = r1;
    }
}

// ---------------------------------------------------------------------------
// Kernel C: output projection + residual; F staged via smem (8x less gmem
// traffic). grid (L/32, NSB) = 512 blocks, block 256:
// thread = (voxel vl 0..31, channel-octet cg 0..7).
// ---------------------------------------------------------------------------
__global__ void __launch_bounds__(256) out_kernel(
    const float* __restrict__ fct, const float* __restrict__ fpet,
    const float* __restrict__ wo, const float* __restrict__ bo,
    float* __restrict__ out)
{
    int vt = blockIdx.x;
    int sb = blockIdx.y;
    int tid = threadIdx.x;
    int vl = tid & 31;
    int cg = tid >> 5;
    int v0 = vt * 32;
    int v = v0 + vl;

    __shared__ float wos[128][66];
    __shared__ float Fs[32][133];     // pad 133: (5*vl + t) banks, conflict-free

    for (int idx = tid; idx < 128 * 64; idx += 256) {
        int c = idx >> 7;
        int t = idx & 127;
        wos[t][c] = wo[idx];
    }
    {   // stage F tile transposed: Fs[v][t] = Fbuf[sb][t][v0+v]
        const float* F = Fbuf + (size_t)sb * L * TD;
#pragma unroll
        for (int i = 0; i < 16; i++) {
            int idx = tid + i * 256;
            int t = idx >> 5, vv = idx & 31;
            Fs[vv][t] = F[(size_t)t * L + v0 + vv];
        }
    }
    __syncthreads();

    u64 accp[4];
#pragma unroll
    for (int i = 0; i < 4; i++) accp[i] = 0ull;

#pragma unroll 16
    for (int t = 0; t < 128; t++) {
        float x = Fs[vl][t];
        u64 xp = pack2(x);
        const u64* wp = (const u64*)&wos[t][cg * 8];
#pragma unroll
        for (int i = 0; i < 4; i++) ffma2(accp[i], xp, wp[i]);
    }

    const float* feat = ((sb >> 1) ? fpet : fct) + (sb & 1) * (CH * L);
    float* o = out + (size_t)sb * CH * L + v;
#pragma unroll
    for (int i = 0; i < 4; i++) {
        float lo, hi;
        unpack2(accp[i], lo, hi);
        int c0 = cg * 8 + 2 * i, c1 = c0 + 1;
        o[(size_t)c0 * L] = feat[(size_t)c0 * L + v] + bo[c0] + lo;
        o[(size_t)c1 * L] = feat[(size_t)c1 * L + v] + bo[c1] + hi;
    }
}

// ---------------------------------------------------------------------------
extern "C" void kernel_launch(void* const* d_in, const int* in_sizes, int n_in,
                              void* d_out, int out_size)
{
    const float* fct  = (const float*)d_in[0];
    const float* fpet = (const float*)d_in[1];
    const float* wq   = (const float*)d_in[2];
    const float* bq   = (const float*)d_in[3];
    const float* wk   = (const float*)d_in[4];
    const float* bk   = (const float*)d_in[5];
    const float* wv   = (const float*)d_in[6];
    const float* bv   = (const float*)d_in[7];
    const float* wo   = (const float*)d_in[8];
    const float* bo   = (const float*)d_in[9];
    float* out = (float*)d_out;

    cudaFuncSetAttribute(attn_mma_kernel,
                         cudaFuncAttributePreferredSharedMemoryCarveout, 100);

    wtrans_kernel<<<(3 * TD * CH + 255) / 256, 256>>>(wq, wk, wv);
    qkv_kernel<<<dim3(L / 16, NSB), 128>>>(fct, fpet, bq, bk, bv);
    attn_mma_kernel<<<dim3(L / 64, NH, NSB), 128>>>();
    out_kernel<<<dim3(L / 32, NSB), 256>>>(fct, fpet, wo, bo, out);
}